// round 5
// baseline (speedup 1.0000x reference)
#include <cuda_runtime.h>
#include <cuda_fp16.h>
#include <cstdint>

// ============================================================
// Problem dims (fixed)
// ============================================================
#define MDIM 8192     // B*S
#define NDIM 4096
#define KDIM 4096
#define NGROUPS 64    // group size 64

// Scratch: half-precision copies (sanctioned __device__ globals)
__device__ __half g_Wh[(size_t)NDIM * KDIM];   // 32 MB
__device__ __half g_Xh[(size_t)MDIM * KDIM];   // 64 MB

// ============================================================
// Pass 1 (merged): dequantize W -> half  AND  convert x -> half
// ============================================================
constexpr int W_BLOCKS = (int)((size_t)NDIM * KDIM / 8 / 256);   // 8192
constexpr int X_BLOCKS = (int)((size_t)MDIM * KDIM / 8 / 256);   // 16384

__global__ void __launch_bounds__(256) convert_kernel(
    const int* __restrict__ q, const float* __restrict__ scale, const float* __restrict__ zp,
    const float* __restrict__ x)
{
    if (blockIdx.x < W_BLOCKS) {
        int idx = blockIdx.x * 256 + threadIdx.x;            // 8 elements per thread
        int n = idx >> 9;                                    // K/8 = 512 per row
        int k = (idx & 511) << 3;
        int g = k >> 6;
        float s = scale[n * NGROUPS + g];
        float z = zp[n * NGROUPS + g];
        int4 q0 = reinterpret_cast<const int4*>(q)[idx * 2 + 0];
        int4 q1 = reinterpret_cast<const int4*>(q)[idx * 2 + 1];
        __half2 h[4];
        h[0] = __floats2half2_rn(((float)q0.x - z) * s, ((float)q0.y - z) * s);
        h[1] = __floats2half2_rn(((float)q0.z - z) * s, ((float)q0.w - z) * s);
        h[2] = __floats2half2_rn(((float)q1.x - z) * s, ((float)q1.y - z) * s);
        h[3] = __floats2half2_rn(((float)q1.z - z) * s, ((float)q1.w - z) * s);
        reinterpret_cast<uint4*>(g_Wh)[idx] = *reinterpret_cast<uint4*>(h);
    } else {
        int idx = (blockIdx.x - W_BLOCKS) * 256 + threadIdx.x;
        float4 a = reinterpret_cast<const float4*>(x)[idx * 2 + 0];
        float4 b = reinterpret_cast<const float4*>(x)[idx * 2 + 1];
        __half2 h[4];
        h[0] = __floats2half2_rn(a.x, a.y);
        h[1] = __floats2half2_rn(a.z, a.w);
        h[2] = __floats2half2_rn(b.x, b.y);
        h[3] = __floats2half2_rn(b.z, b.w);
        reinterpret_cast<uint4*>(g_Xh)[idx] = *reinterpret_cast<uint4*>(h);
    }
}

// ============================================================
// Pass 2: GEMM  out[M,N] = Xh @ Wh^T + bias   (fp16 in, fp32 acc)
// CTA 128x128, 4 warps, warp tile 64x64 (2Mx2N), KS=64, 3 stages.
// 2 CTAs/SM. Warp 64x64 halves smem read traffic vs 64x32.
// ============================================================
constexpr int TILE_M = 128;
constexpr int TILE_N = 128;
constexpr int KS = 64;
constexpr int NSTAGE = 3;
constexpr int NKS = KDIM / KS;                  // 64
constexpr int A_STAGE_B = TILE_M * 128;         // 16 KB
constexpr int STAGE_B = 2 * A_STAGE_B;          // 32 KB
constexpr int SMEM_BYTES = 1024 + NSTAGE * STAGE_B;  // 99328 (1KB align pad)

__device__ __forceinline__ uint32_t smem_u32(const void* p) {
    uint32_t a;
    asm("{ .reg .u64 t; cvta.to.shared.u64 t, %1; cvt.u32.u64 %0, t; }" : "=r"(a) : "l"(p));
    return a;
}
__device__ __forceinline__ void cp_async16(uint32_t dst, const void* src) {
    asm volatile("cp.async.cg.shared.global [%0], [%1], 16;" :: "r"(dst), "l"(src));
}
__device__ __forceinline__ void cp_commit() {
    asm volatile("cp.async.commit_group;" ::: "memory");
}
template <int N>
__device__ __forceinline__ void cp_wait() {
    asm volatile("cp.async.wait_group %0;" :: "n"(N) : "memory");
}
__device__ __forceinline__ void ldmatrix_x4(uint32_t* r, uint32_t addr) {
    asm volatile("ldmatrix.sync.aligned.m8n8.x4.shared.b16 {%0,%1,%2,%3}, [%4];"
                 : "=r"(r[0]), "=r"(r[1]), "=r"(r[2]), "=r"(r[3]) : "r"(addr));
}
__device__ __forceinline__ void mma16816(float* c, const uint32_t* a, uint32_t b0, uint32_t b1) {
    asm volatile(
        "mma.sync.aligned.m16n8k16.row.col.f32.f16.f16.f32 "
        "{%0,%1,%2,%3}, {%4,%5,%6,%7}, {%8,%9}, {%0,%1,%2,%3};"
        : "+f"(c[0]), "+f"(c[1]), "+f"(c[2]), "+f"(c[3])
        : "r"(a[0]), "r"(a[1]), "r"(a[2]), "r"(a[3]), "r"(b0), "r"(b1));
}

__global__ void __launch_bounds__(128, 2) gemm_kernel(
    const float* __restrict__ bias, float* __restrict__ out)
{
    extern __shared__ char smem[];
    const uint32_t sb = (smem_u32(smem) + 1023u) & ~1023u;   // 1KB aligned -> XOR swizzle valid
    const int tid = threadIdx.x;
    const int wid = tid >> 5;        // 0..3
    const int lane = tid & 31;

    const int m_base = blockIdx.y * TILE_M;
    const int n_base = blockIdx.x * TILE_N;
    const int warp_m = (wid >> 1) * 64;   // 2 warps along M
    const int warp_n = (wid & 1) * 64;    // 2 warps along N

    // ---------- cp.async addressing: thread owns row `tid` of A and of B (8 x 16B each) ----------
    const __half* gA = g_Xh + (size_t)(m_base + tid) * KDIM;
    const __half* gB = g_Wh + (size_t)(n_base + tid) * KDIM;
    // base offsets such that dst = (stagebase + off) ^ (c*16), c = 0..7
    const uint32_t cpoffA = (uint32_t)(tid * 128 + (tid & 7) * 16);
    const uint32_t cpoffB = cpoffA + (uint32_t)A_STAGE_B;

    auto issue_full_stage = [&](int ks, int stage) {
        uint32_t base = sb + stage * STAGE_B;
        const __half* a = gA + ks * KS;
        const __half* b = gB + ks * KS;
        #pragma unroll
        for (int c = 0; c < 8; c++) cp_async16((base + cpoffA) ^ (uint32_t)(c * 16), a + c * 8);
        #pragma unroll
        for (int c = 0; c < 8; c++) cp_async16((base + cpoffB) ^ (uint32_t)(c * 16), b + c * 8);
    };

    issue_full_stage(0, 0); cp_commit();
    issue_full_stage(1, 1); cp_commit();

    float acc[4][8][4];
    #pragma unroll
    for (int i = 0; i < 4; i++)
        #pragma unroll
        for (int j = 0; j < 8; j++)
            #pragma unroll
            for (int r = 0; r < 4; r++) acc[i][j][r] = 0.f;

    // ldmatrix lane addressing: addr = (base + rb) ^ (kk*32); rb folds lhc into swizzle bits
    const int lrow = lane & 15;
    const int lhc = lane >> 4;
    const uint32_t lxor = (uint32_t)((((lrow & 7) ^ lhc) * 16));
    uint32_t rbA[4], rbB[4];
    #pragma unroll
    for (int i = 0; i < 4; i++) {
        rbA[i] = (uint32_t)((warp_m + i * 16 + lrow) * 128) + lxor;
        rbB[i] = (uint32_t)(A_STAGE_B + (warp_n + i * 16 + lrow) * 128) + lxor;
    }

    uint32_t af[2][4][4], bf[2][4][4];   // double-buffered fragments

    int stage = 0;
    for (int ks = 0; ks < NKS; ks++) {
        cp_wait<1>();
        __syncthreads();

        const uint32_t abase = sb + stage * STAGE_B;
        const bool pref = (ks + 2 < NKS);
        const int pstage = (stage + 2 >= NSTAGE) ? stage + 2 - NSTAGE : stage + 2;
        const uint32_t pbase = sb + pstage * STAGE_B;
        const __half* pA = gA + (ks + 2) * KS;
        const __half* pB = gB + (ks + 2) * KS;

        // kk=0 fragment burst (buf 0)
        #pragma unroll
        for (int i = 0; i < 4; i++) ldmatrix_x4(af[0][i], abase + rbA[i]);
        #pragma unroll
        for (int i = 0; i < 4; i++) ldmatrix_x4(bf[0][i], abase + rbB[i]);

        #pragma unroll
        for (int kk = 0; kk < 4; kk++) {
            const int mb = kk & 1;
            const int lb = (kk + 1) & 1;
            const bool dl = (kk < 3);
            const uint32_t kx = (uint32_t)((kk + 1) * 32);

            #pragma unroll
            for (int t = 0; t < 16; t++) {
                const int i = t >> 2;
                const int jj = t & 3;
                // interleave: 8 LDSM(kk+1) across first 8 MMA pairs
                if (dl && t < 4)            ldmatrix_x4(af[lb][t], (abase + rbA[t]) ^ kx);
                if (dl && t >= 4 && t < 8)  ldmatrix_x4(bf[lb][t - 4], (abase + rbB[t - 4]) ^ kx);
                // 4 cp.async for stage+2 across later MMA pairs
                if (pref && t == 8)
                    cp_async16((pbase + cpoffA) ^ (uint32_t)((2 * kk + 0) * 16), pA + (2 * kk + 0) * 8);
                if (pref && t == 10)
                    cp_async16((pbase + cpoffA) ^ (uint32_t)((2 * kk + 1) * 16), pA + (2 * kk + 1) * 8);
                if (pref && t == 12)
                    cp_async16((pbase + cpoffB) ^ (uint32_t)((2 * kk + 0) * 16), pB + (2 * kk + 0) * 8);
                if (pref && t == 14)
                    cp_async16((pbase + cpoffB) ^ (uint32_t)((2 * kk + 1) * 16), pB + (2 * kk + 1) * 8);

                mma16816(acc[i][2 * jj + 0], af[mb][i], bf[mb][jj][0], bf[mb][jj][2]);
                mma16816(acc[i][2 * jj + 1], af[mb][i], bf[mb][jj][1], bf[mb][jj][3]);
            }
            if (kk == 3) cp_commit();
        }
        stage = (stage + 1 >= NSTAGE) ? 0 : stage + 1;
    }

    // ---------- epilogue: bias + store ----------
    const int qm = lane >> 2;            // 0..7
    const int qn = (lane & 3) * 2;       // 0,2,4,6
    #pragma unroll
    for (int j = 0; j < 8; j++) {        // 8 n8 tiles across warp_n..+64
        int n0 = n_base + warp_n + j * 8 + qn;
        float2 bv = *reinterpret_cast<const float2*>(bias + n0);
        #pragma unroll
        for (int i = 0; i < 4; i++) {
            int m0 = m_base + warp_m + i * 16 + qm;
            float2 v0 = { acc[i][j][0] + bv.x, acc[i][j][1] + bv.y };
            float2 v1 = { acc[i][j][2] + bv.x, acc[i][j][3] + bv.y };
            *reinterpret_cast<float2*>(out + (size_t)m0 * NDIM + n0) = v0;
            *reinterpret_cast<float2*>(out + (size_t)(m0 + 8) * NDIM + n0) = v1;
        }
    }
}

// ============================================================
// Launch
// ============================================================
extern "C" void kernel_launch(void* const* d_in, const int* in_sizes, int n_in,
                              void* d_out, int out_size) {
    const float* x     = (const float*)d_in[0];
    const int*   wq    = (const int*)d_in[1];
    const float* scale = (const float*)d_in[2];
    const float* zp    = (const float*)d_in[3];
    const float* bias  = (const float*)d_in[4];
    float* out = (float*)d_out;

    convert_kernel<<<W_BLOCKS + X_BLOCKS, 256>>>(wq, scale, zp, x);

    static bool attr_set = false;
    if (!attr_set) {
        cudaFuncSetAttribute(gemm_kernel, cudaFuncAttributeMaxDynamicSharedMemorySize, SMEM_BYTES);
        attr_set = true;
    }
    dim3 grid(NDIM / TILE_N, MDIM / TILE_M);   // (32, 64)
    gemm_kernel<<<grid, 128, SMEM_BYTES>>>(bias, out);
}

// round 7
// speedup vs baseline: 1.6552x; 1.6552x over previous
#include <cuda_runtime.h>
#include <cuda_fp16.h>
#include <cstdint>

// ============================================================
// Problem dims (fixed)
// ============================================================
#define MDIM 8192     // B*S
#define NDIM 4096
#define KDIM 4096
#define NGROUPS 64    // group size 64

// Scratch: half-precision copies (sanctioned __device__ globals)
__device__ __half g_Wh[(size_t)NDIM * KDIM];   // 32 MB
__device__ __half g_Xh[(size_t)MDIM * KDIM];   // 64 MB

// ============================================================
// Pass 1 (merged): dequantize W -> half  AND  convert x -> half
// ============================================================
constexpr int W_BLOCKS = (int)((size_t)NDIM * KDIM / 8 / 256);   // 8192
constexpr int X_BLOCKS = (int)((size_t)MDIM * KDIM / 8 / 256);   // 16384

__global__ void __launch_bounds__(256) convert_kernel(
    const int* __restrict__ q, const float* __restrict__ scale, const float* __restrict__ zp,
    const float* __restrict__ x)
{
    if (blockIdx.x < W_BLOCKS) {
        int idx = blockIdx.x * 256 + threadIdx.x;            // 8 elements per thread
        int n = idx >> 9;                                    // K/8 = 512 per row
        int k = (idx & 511) << 3;
        int g = k >> 6;
        float s = scale[n * NGROUPS + g];
        float z = zp[n * NGROUPS + g];
        int4 q0 = reinterpret_cast<const int4*>(q)[idx * 2 + 0];
        int4 q1 = reinterpret_cast<const int4*>(q)[idx * 2 + 1];
        __half2 h[4];
        h[0] = __floats2half2_rn(((float)q0.x - z) * s, ((float)q0.y - z) * s);
        h[1] = __floats2half2_rn(((float)q0.z - z) * s, ((float)q0.w - z) * s);
        h[2] = __floats2half2_rn(((float)q1.x - z) * s, ((float)q1.y - z) * s);
        h[3] = __floats2half2_rn(((float)q1.z - z) * s, ((float)q1.w - z) * s);
        reinterpret_cast<uint4*>(g_Wh)[idx] = *reinterpret_cast<uint4*>(h);
    } else {
        int idx = (blockIdx.x - W_BLOCKS) * 256 + threadIdx.x;
        float4 a = reinterpret_cast<const float4*>(x)[idx * 2 + 0];
        float4 b = reinterpret_cast<const float4*>(x)[idx * 2 + 1];
        __half2 h[4];
        h[0] = __floats2half2_rn(a.x, a.y);
        h[1] = __floats2half2_rn(a.z, a.w);
        h[2] = __floats2half2_rn(b.x, b.y);
        h[3] = __floats2half2_rn(b.z, b.w);
        reinterpret_cast<uint4*>(g_Xh)[idx] = *reinterpret_cast<uint4*>(h);
    }
}

// ============================================================
// Pass 2: GEMM  out[M,N] = Xh @ Wh^T + bias   (fp16 in, fp32 acc)
// CTA 256x128, 8 warps (warp 64x64, grid 4Mx2N), KS=64, 4 stages.
// 1 CTA/SM (192 KB smem), 256-reg budget. 64x64 warp tile cuts LDSM
// wavefronts; 4-stage distance-3 cp.async pipeline absorbs barrier jitter.
// ============================================================
constexpr int TILE_M = 256;
constexpr int TILE_N = 128;
constexpr int KS = 64;
constexpr int NSTAGE = 4;
constexpr int NKS = KDIM / KS;                  // 64
constexpr int A_STAGE_B = TILE_M * 128;         // 32 KB
constexpr int B_STAGE_B = TILE_N * 128;         // 16 KB
constexpr int STAGE_B = A_STAGE_B + B_STAGE_B;  // 48 KB
constexpr int SMEM_BYTES = 1024 + NSTAGE * STAGE_B;  // 197632 (1KB align pad)

__device__ __forceinline__ uint32_t smem_u32(const void* p) {
    uint32_t a;
    asm("{ .reg .u64 t; cvta.to.shared.u64 t, %1; cvt.u32.u64 %0, t; }" : "=r"(a) : "l"(p));
    return a;
}
__device__ __forceinline__ void cp_async16(uint32_t dst, const void* src) {
    asm volatile("cp.async.cg.shared.global [%0], [%1], 16;" :: "r"(dst), "l"(src));
}
__device__ __forceinline__ void cp_commit() {
    asm volatile("cp.async.commit_group;" ::: "memory");
}
template <int N>
__device__ __forceinline__ void cp_wait() {
    asm volatile("cp.async.wait_group %0;" :: "n"(N) : "memory");
}
__device__ __forceinline__ void ldmatrix_x4(uint32_t* r, uint32_t addr) {
    asm volatile("ldmatrix.sync.aligned.m8n8.x4.shared.b16 {%0,%1,%2,%3}, [%4];"
                 : "=r"(r[0]), "=r"(r[1]), "=r"(r[2]), "=r"(r[3]) : "r"(addr));
}
__device__ __forceinline__ void mma16816(float* c, const uint32_t* a, uint32_t b0, uint32_t b1) {
    asm volatile(
        "mma.sync.aligned.m16n8k16.row.col.f32.f16.f16.f32 "
        "{%0,%1,%2,%3}, {%4,%5,%6,%7}, {%8,%9}, {%0,%1,%2,%3};"
        : "+f"(c[0]), "+f"(c[1]), "+f"(c[2]), "+f"(c[3])
        : "r"(a[0]), "r"(a[1]), "r"(a[2]), "r"(a[3]), "r"(b0), "r"(b1));
}

__global__ void __launch_bounds__(256, 1) gemm_kernel(
    const float* __restrict__ bias, float* __restrict__ out)
{
    extern __shared__ char smem[];
    const uint32_t sb = (smem_u32(smem) + 1023u) & ~1023u;   // 1KB aligned
    const int tid = threadIdx.x;
    const int wid = tid >> 5;        // 0..7
    const int lane = tid & 31;

    const int m_base = blockIdx.y * TILE_M;
    const int n_base = blockIdx.x * TILE_N;
    const int warp_m = (wid >> 1) * 64;   // 4 warps along M: 0,64,128,192
    const int warp_n = (wid & 1) * 64;    // 2 warps along N: 0,64

    // ---------- cp.async addressing ----------
    // A: thread owns row tid (8 x 16B chunks). B: row tid&127, 4 chunks starting (tid>>7)*4.
    const int brow = tid & 127;
    const int bcs = (tid >> 7) * 4;
    const __half* gA = g_Xh + (size_t)(m_base + tid) * KDIM;
    const __half* gB = g_Wh + (size_t)(n_base + brow) * KDIM;

    // 12 chunk slots: 0..7 = A chunk c, 8..11 = B chunk bcs+c
    uint32_t cpOff[12];
    uint32_t cpSrcOff[12];   // element offset within the row for this chunk
    #pragma unroll
    for (int c = 0; c < 8; c++) {
        cpOff[c] = (uint32_t)(tid * 128 + (((tid & 7) ^ c) * 16));
        cpSrcOff[c] = (uint32_t)(c * 8);
    }
    #pragma unroll
    for (int c = 0; c < 4; c++) {
        cpOff[8 + c] = (uint32_t)(A_STAGE_B + brow * 128 + (((brow & 7) ^ (bcs + c)) * 16));
        cpSrcOff[8 + c] = (uint32_t)((bcs + c) * 8);
    }

    auto issue_full_stage = [&](int ks, int stage) {
        uint32_t base = sb + stage * STAGE_B;
        const __half* a = gA + ks * KS;
        const __half* b = gB + ks * KS;
        #pragma unroll
        for (int c = 0; c < 8; c++)  cp_async16(base + cpOff[c], a + cpSrcOff[c]);
        #pragma unroll
        for (int c = 8; c < 12; c++) cp_async16(base + cpOff[c], b + cpSrcOff[c]);
    };

    // prologue: 3 stages in flight (distance 3)
    issue_full_stage(0, 0); cp_commit();
    issue_full_stage(1, 1); cp_commit();
    issue_full_stage(2, 2); cp_commit();

    float acc[4][8][4];
    #pragma unroll
    for (int i = 0; i < 4; i++)
        #pragma unroll
        for (int j = 0; j < 8; j++)
            #pragma unroll
            for (int r = 0; r < 4; r++) acc[i][j][r] = 0.f;

    // ldmatrix lane addressing: addr = (stagebase + rb) ^ (kk*32)
    const int lrow = lane & 15;
    const int lhc = lane >> 4;
    const uint32_t lxor = (uint32_t)(((lrow & 7) ^ lhc) * 16);
    uint32_t rbA[4], rbB[4];
    #pragma unroll
    for (int i = 0; i < 4; i++) {
        rbA[i] = (uint32_t)((warp_m + i * 16 + lrow) * 128) + lxor;
        rbB[i] = (uint32_t)(A_STAGE_B + (warp_n + i * 16 + lrow) * 128) + lxor;
    }

    uint32_t af[2][4][4], bf[2][4][4];   // double-buffered fragments

    int stage = 0;
    for (int ks = 0; ks < NKS; ks++) {
        cp_wait<2>();
        __syncthreads();

        const uint32_t abase = sb + stage * STAGE_B;
        const bool pref = (ks + 3 < NKS);
        const int pstage = (stage + 3 >= NSTAGE) ? stage + 3 - NSTAGE : stage + 3;
        const uint32_t pbase = sb + pstage * STAGE_B;
        const __half* pA = gA + (ks + 3) * KS;
        const __half* pB = gB + (ks + 3) * KS;

        // kk=0 fragment burst (buf 0)
        #pragma unroll
        for (int i = 0; i < 4; i++) ldmatrix_x4(af[0][i], abase + rbA[i]);
        #pragma unroll
        for (int i = 0; i < 4; i++) ldmatrix_x4(bf[0][i], abase + rbB[i]);

        #pragma unroll
        for (int kk = 0; kk < 4; kk++) {
            const int mb = kk & 1;
            const int lb = (kk + 1) & 1;
            const bool dl = (kk < 3);
            const uint32_t kx = (uint32_t)((kk + 1) * 32);

            #pragma unroll
            for (int t = 0; t < 16; t++) {
                const int i = t >> 2;
                const int jj = t & 3;
                // interleave: 8 LDSM(kk+1) across first 8 MMA pairs
                if (dl && t < 4)            ldmatrix_x4(af[lb][t], (abase + rbA[t]) ^ kx);
                if (dl && t >= 4 && t < 8)  ldmatrix_x4(bf[lb][t - 4], (abase + rbB[t - 4]) ^ kx);
                // 3 cp.async for stage+3, spread across later MMA pairs
                if (pref && t == 9) {
                    const int c = 3 * kk + 0;
                    cp_async16(pbase + cpOff[c], (c < 8 ? pA : pB) + cpSrcOff[c]);
                }
                if (pref && t == 11) {
                    const int c = 3 * kk + 1;
                    cp_async16(pbase + cpOff[c], (c < 8 ? pA : pB) + cpSrcOff[c]);
                }
                if (pref && t == 13) {
                    const int c = 3 * kk + 2;
                    cp_async16(pbase + cpOff[c], (c < 8 ? pA : pB) + cpSrcOff[c]);
                }

                mma16816(acc[i][2 * jj + 0], af[mb][i], bf[mb][jj][0], bf[mb][jj][2]);
                mma16816(acc[i][2 * jj + 1], af[mb][i], bf[mb][jj][1], bf[mb][jj][3]);
            }
            if (kk == 3) cp_commit();
        }
        stage = (stage + 1 >= NSTAGE) ? 0 : stage + 1;
    }

    // ---------- epilogue: bias + store ----------
    const int qm = lane >> 2;            // 0..7
    const int qn = (lane & 3) * 2;       // 0,2,4,6
    #pragma unroll
    for (int j = 0; j < 8; j++) {        // 8 n8 tiles across warp_n..+64
        int n0 = n_base + warp_n + j * 8 + qn;
        float2 bv = *reinterpret_cast<const float2*>(bias + n0);
        #pragma unroll
        for (int i = 0; i < 4; i++) {
            int m0 = m_base + warp_m + i * 16 + qm;
            float2 v0 = { acc[i][j][0] + bv.x, acc[i][j][1] + bv.y };
            float2 v1 = { acc[i][j][2] + bv.x, acc[i][j][3] + bv.y };
            *reinterpret_cast<float2*>(out + (size_t)m0 * NDIM + n0) = v0;
            *reinterpret_cast<float2*>(out + (size_t)(m0 + 8) * NDIM + n0) = v1;
        }
    }
}

// ============================================================
// Launch
// ============================================================
extern "C" void kernel_launch(void* const* d_in, const int* in_sizes, int n_in,
                              void* d_out, int out_size) {
    const float* x     = (const float*)d_in[0];
    const int*   wq    = (const int*)d_in[1];
    const float* scale = (const float*)d_in[2];
    const float* zp    = (const float*)d_in[3];
    const float* bias  = (const float*)d_in[4];
    float* out = (float*)d_out;

    convert_kernel<<<W_BLOCKS + X_BLOCKS, 256>>>(wq, scale, zp, x);

    static bool attr_set = false;
    if (!attr_set) {
        cudaFuncSetAttribute(gemm_kernel, cudaFuncAttributeMaxDynamicSharedMemorySize, SMEM_BYTES);
        attr_set = true;
    }
    dim3 grid(NDIM / TILE_N, MDIM / TILE_M);   // (32, 32)
    gemm_kernel<<<grid, 256, SMEM_BYTES>>>(bias, out);
}

// round 10
// speedup vs baseline: 2.5851x; 1.5618x over previous
#include <cuda_runtime.h>
#include <cuda_fp16.h>
#include <cstdint>

// ============================================================
// Problem dims (fixed)
// ============================================================
#define MDIM 8192     // B*S
#define NDIM 4096
#define KDIM 4096
#define NGROUPS 64    // group size 64

constexpr int TILE_M = 128;
constexpr int TILE_N = 128;
constexpr int KS = 64;                     // halves per K-stage (128 B rows)
constexpr int NKS = KDIM / KS;             // 64
constexpr int TILE_BYTES = TILE_M * 128;   // 16 KB per operand tile-stage
constexpr int NSTAGE = 3;
constexpr int STAGE_B = 2 * TILE_BYTES;    // 32 KB
constexpr int SMEM_BYTES = 2048 + NSTAGE * STAGE_B;   // pad for 1KB align + mbars

// Scratch: half tiles pre-laid-out in GEMM's per-stage swizzled format.
// tile(i, ks) = 16KB contiguous: row r (128 rows) x 8 swizzled 16B chunks.
__device__ __half g_Wt[(size_t)NDIM * KDIM];   // 32 MB, tiles indexed (nt*NKS + ks)
__device__ __half g_Xt[(size_t)MDIM * KDIM];   // 64 MB, tiles indexed (mt*NKS + ks)

// ============================================================
// Pass 1 (merged): dequant W and convert X directly into tiled+swizzled layout.
// One thread = one 16B output chunk. ks == quant group index (group size == KS).
// ============================================================
constexpr int W_CHUNKS = (int)((size_t)NDIM * KDIM * 2 / 16);   // 2M
constexpr int X_CHUNKS = (int)((size_t)MDIM * KDIM * 2 / 16);   // 8M
constexpr int W_BLOCKS = W_CHUNKS / 256;                        // 8192
constexpr int X_BLOCKS = X_CHUNKS / 256;                        // 32768

__global__ void __launch_bounds__(256) convert_kernel(
    const int* __restrict__ q, const float* __restrict__ scale, const float* __restrict__ zp,
    const float* __restrict__ x)
{
    if (blockIdx.x < W_BLOCKS) {
        int t = blockIdx.x * 256 + threadIdx.x;     // target 16B chunk index
        int idx = t & 1023;                         // chunk within 16KB tile
        int tile = t >> 10;                         // nt*NKS + ks
        int ks = tile & (NKS - 1);
        int nt = tile >> 6;
        int r = idx >> 3;
        int cS = idx & 7;
        int c = cS ^ (r & 7);                       // un-swizzled chunk
        int n = nt * 128 + r;
        int k = ks * KS + c * 8;
        const int4* qp = reinterpret_cast<const int4*>(q + (size_t)n * KDIM + k);
        int4 q0 = qp[0], q1 = qp[1];
        float s = scale[n * NGROUPS + ks];          // group == ks (G == KS == 64)
        float z = zp[n * NGROUPS + ks];
        __half2 h[4];
        h[0] = __floats2half2_rn(((float)q0.x - z) * s, ((float)q0.y - z) * s);
        h[1] = __floats2half2_rn(((float)q0.z - z) * s, ((float)q0.w - z) * s);
        h[2] = __floats2half2_rn(((float)q1.x - z) * s, ((float)q1.y - z) * s);
        h[3] = __floats2half2_rn(((float)q1.z - z) * s, ((float)q1.w - z) * s);
        reinterpret_cast<uint4*>(g_Wt)[t] = *reinterpret_cast<uint4*>(h);
    } else {
        int t = (blockIdx.x - W_BLOCKS) * 256 + threadIdx.x;
        int idx = t & 1023;
        int tile = t >> 10;                         // mt*NKS + ks
        int ks = tile & (NKS - 1);
        int mt = tile >> 6;
        int r = idx >> 3;
        int cS = idx & 7;
        int c = cS ^ (r & 7);
        int m = mt * 128 + r;
        int k = ks * KS + c * 8;
        const float4* xp = reinterpret_cast<const float4*>(x + (size_t)m * KDIM + k);
        float4 a = xp[0], b = xp[1];
        __half2 h[4];
        h[0] = __floats2half2_rn(a.x, a.y);
        h[1] = __floats2half2_rn(a.z, a.w);
        h[2] = __floats2half2_rn(b.x, b.y);
        h[3] = __floats2half2_rn(b.z, b.w);
        reinterpret_cast<uint4*>(g_Xt)[t] = *reinterpret_cast<uint4*>(h);
    }
}

// ============================================================
// Pass 2: GEMM  out[M,N] = X @ W^T + bias   (fp16 in, fp32 acc)
// CTA 128x128, 8 warps (warp 64x32), 3 stages, 2 CTAs/SM.
// Stage loads = 2 x 16KB cp.async.bulk issued by ONE thread -> zero LDGSTS
// pressure in compute warps. mbarrier(expect_tx) completion, distance-2.
// ============================================================
__device__ __forceinline__ uint32_t smem_u32(const void* p) {
    uint32_t a;
    asm("{ .reg .u64 t; cvta.to.shared.u64 t, %1; cvt.u32.u64 %0, t; }" : "=r"(a) : "l"(p));
    return a;
}
__device__ __forceinline__ void mbar_init(uint32_t addr, uint32_t cnt) {
    asm volatile("mbarrier.init.shared.b64 [%0], %1;" :: "r"(addr), "r"(cnt) : "memory");
}
__device__ __forceinline__ void mbar_expect_tx(uint32_t addr, uint32_t bytes) {
    asm volatile("mbarrier.arrive.expect_tx.shared.b64 _, [%0], %1;"
                 :: "r"(addr), "r"(bytes) : "memory");
}
__device__ __forceinline__ void mbar_wait(uint32_t mbar, uint32_t parity) {
    uint32_t done;
    asm volatile("{\n\t.reg .pred p;\n\t"
        "mbarrier.try_wait.parity.acquire.cta.shared::cta.b64 p, [%1], %2;\n\t"
        "selp.b32 %0, 1, 0, p;\n\t}"
        : "=r"(done) : "r"(mbar), "r"(parity) : "memory");
    while (!done) {
        asm volatile("{\n\t.reg .pred p;\n\t"
            "mbarrier.try_wait.parity.acquire.cta.shared::cta.b64 p, [%1], %2, 0x989680;\n\t"
            "selp.b32 %0, 1, 0, p;\n\t}"
            : "=r"(done) : "r"(mbar), "r"(parity) : "memory");
    }
}
__device__ __forceinline__ void bulk_g2s(uint32_t dst, const void* src, uint32_t bytes,
                                         uint32_t mbar) {
    asm volatile(
        "cp.async.bulk.shared::cluster.global.mbarrier::complete_tx::bytes [%0], [%1], %2, [%3];"
        :: "r"(dst), "l"(src), "r"(bytes), "r"(mbar) : "memory");
}
__device__ __forceinline__ void ldmatrix_x4(uint32_t* r, uint32_t addr) {
    asm volatile("ldmatrix.sync.aligned.m8n8.x4.shared.b16 {%0,%1,%2,%3}, [%4];"
                 : "=r"(r[0]), "=r"(r[1]), "=r"(r[2]), "=r"(r[3]) : "r"(addr));
}
__device__ __forceinline__ void mma16816(float* c, const uint32_t* a, uint32_t b0, uint32_t b1) {
    asm volatile(
        "mma.sync.aligned.m16n8k16.row.col.f32.f16.f16.f32 "
        "{%0,%1,%2,%3}, {%4,%5,%6,%7}, {%8,%9}, {%0,%1,%2,%3};"
        : "+f"(c[0]), "+f"(c[1]), "+f"(c[2]), "+f"(c[3])
        : "r"(a[0]), "r"(a[1]), "r"(a[2]), "r"(a[3]), "r"(b0), "r"(b1));
}

__global__ void __launch_bounds__(256, 2) gemm_kernel(
    const float* __restrict__ bias, float* __restrict__ out)
{
    extern __shared__ char smem[];
    const uint32_t raw = smem_u32(smem);
    const uint32_t mb = raw;                                    // 3 mbarriers (8B each)
    const uint32_t sb = (raw + 64 + 1023u) & ~1023u;            // 1KB-aligned stage base
    const int tid = threadIdx.x;
    const int wid = tid >> 5;
    const int lane = tid & 31;

    const int nt = blockIdx.x;
    const int mt = blockIdx.y;
    const int warp_m = (wid >> 2) * 64;   // 2 warps along M
    const int warp_n = (wid & 3) * 32;    // 4 warps along N

    const char* baseA = (const char*)g_Xt + (size_t)mt * NKS * TILE_BYTES;
    const char* baseB = (const char*)g_Wt + (size_t)nt * NKS * TILE_BYTES;

    if (tid == 0) {
        mbar_init(mb + 0, 1);
        mbar_init(mb + 8, 1);
        mbar_init(mb + 16, 1);
        asm volatile("fence.proxy.async;" ::: "memory");
    }
    __syncthreads();

    auto issue = [&](int ks, int st) {
        if (tid == 0) {
            uint32_t bar = mb + st * 8;
            mbar_expect_tx(bar, (uint32_t)STAGE_B);
            bulk_g2s(sb + st * STAGE_B, baseA + (size_t)ks * TILE_BYTES,
                     (uint32_t)TILE_BYTES, bar);
            bulk_g2s(sb + st * STAGE_B + TILE_BYTES, baseB + (size_t)ks * TILE_BYTES,
                     (uint32_t)TILE_BYTES, bar);
        }
    };

    issue(0, 0);
    issue(1, 1);

    float acc[4][4][4];
    #pragma unroll
    for (int i = 0; i < 4; i++)
        #pragma unroll
        for (int j = 0; j < 4; j++)
            #pragma unroll
            for (int r = 0; r < 4; r++) acc[i][j][r] = 0.f;

    // ldmatrix lane addressing: addr = (stagebase + rb) ^ (kk*32)
    const int lrow = lane & 15;
    const int lhc = lane >> 4;
    const uint32_t lxor = (uint32_t)(((lrow & 7) ^ lhc) * 16);
    uint32_t rbA[4], rbB[2];
    #pragma unroll
    for (int i = 0; i < 4; i++)
        rbA[i] = (uint32_t)((warp_m + i * 16 + lrow) * 128) + lxor;
    #pragma unroll
    for (int j = 0; j < 2; j++)
        rbB[j] = (uint32_t)(TILE_BYTES + (warp_n + j * 16 + lrow) * 128) + lxor;

    uint32_t af[2][4][4], bf[2][2][4];   // double-buffered fragments

    int stage = 0, phase = 0;
    for (int ks = 0; ks < NKS; ks++) {
        mbar_wait(mb + stage * 8, (uint32_t)phase);
        __syncthreads();
        if (ks + 2 < NKS) issue(ks + 2, (stage + 2 >= NSTAGE) ? stage + 2 - NSTAGE : stage + 2);

        const uint32_t abase = sb + stage * STAGE_B;

        // kk=0 fragment burst (buf 0)
        #pragma unroll
        for (int i = 0; i < 4; i++) ldmatrix_x4(af[0][i], abase + rbA[i]);
        #pragma unroll
        for (int j = 0; j < 2; j++) ldmatrix_x4(bf[0][j], abase + rbB[j]);

        #pragma unroll
        for (int kk = 0; kk < 4; kk++) {
            const int mbuf = kk & 1;
            const int lb = (kk + 1) & 1;
            const bool dl = (kk < 3);
            const uint32_t kx = (uint32_t)((kk + 1) * 32);

            // interleaved: 6 LDSM(kk+1) spread between MMA pairs
            if (dl) ldmatrix_x4(af[lb][0], (abase + rbA[0]) ^ kx);
            mma16816(acc[0][0], af[mbuf][0], bf[mbuf][0][0], bf[mbuf][0][2]);
            mma16816(acc[0][1], af[mbuf][0], bf[mbuf][0][1], bf[mbuf][0][3]);
            if (dl) ldmatrix_x4(af[lb][1], (abase + rbA[1]) ^ kx);
            mma16816(acc[0][2], af[mbuf][0], bf[mbuf][1][0], bf[mbuf][1][2]);
            mma16816(acc[0][3], af[mbuf][0], bf[mbuf][1][1], bf[mbuf][1][3]);
            if (dl) ldmatrix_x4(af[lb][2], (abase + rbA[2]) ^ kx);
            mma16816(acc[1][0], af[mbuf][1], bf[mbuf][0][0], bf[mbuf][0][2]);
            mma16816(acc[1][1], af[mbuf][1], bf[mbuf][0][1], bf[mbuf][0][3]);
            if (dl) ldmatrix_x4(af[lb][3], (abase + rbA[3]) ^ kx);
            mma16816(acc[1][2], af[mbuf][1], bf[mbuf][1][0], bf[mbuf][1][2]);
            mma16816(acc[1][3], af[mbuf][1], bf[mbuf][1][1], bf[mbuf][1][3]);
            if (dl) ldmatrix_x4(bf[lb][0], (abase + rbB[0]) ^ kx);
            mma16816(acc[2][0], af[mbuf][2], bf[mbuf][0][0], bf[mbuf][0][2]);
            mma16816(acc[2][1], af[mbuf][2], bf[mbuf][0][1], bf[mbuf][0][3]);
            if (dl) ldmatrix_x4(bf[lb][1], (abase + rbB[1]) ^ kx);
            mma16816(acc[2][2], af[mbuf][2], bf[mbuf][1][0], bf[mbuf][1][2]);
            mma16816(acc[2][3], af[mbuf][2], bf[mbuf][1][1], bf[mbuf][1][3]);
            mma16816(acc[3][0], af[mbuf][3], bf[mbuf][0][0], bf[mbuf][0][2]);
            mma16816(acc[3][1], af[mbuf][3], bf[mbuf][0][1], bf[mbuf][0][3]);
            mma16816(acc[3][2], af[mbuf][3], bf[mbuf][1][0], bf[mbuf][1][2]);
            mma16816(acc[3][3], af[mbuf][3], bf[mbuf][1][1], bf[mbuf][1][3]);
        }
        if (++stage == NSTAGE) { stage = 0; phase ^= 1; }
    }

    // ---------- epilogue: bias + store ----------
    const int qm = lane >> 2;            // 0..7
    const int qn = (lane & 3) * 2;       // 0,2,4,6
    #pragma unroll
    for (int j = 0; j < 4; j++) {
        int n0 = nt * TILE_N + warp_n + j * 8 + qn;
        float2 bv = *reinterpret_cast<const float2*>(bias + n0);
        #pragma unroll
        for (int i = 0; i < 4; i++) {
            int m0 = mt * TILE_M + warp_m + i * 16 + qm;
            float2 v0 = { acc[i][j][0] + bv.x, acc[i][j][1] + bv.y };
            float2 v1 = { acc[i][j][2] + bv.x, acc[i][j][3] + bv.y };
            *reinterpret_cast<float2*>(out + (size_t)m0 * NDIM + n0) = v0;
            *reinterpret_cast<float2*>(out + (size_t)(m0 + 8) * NDIM + n0) = v1;
        }
    }
}

// ============================================================
// Launch
// ============================================================
extern "C" void kernel_launch(void* const* d_in, const int* in_sizes, int n_in,
                              void* d_out, int out_size) {
    const float* x     = (const float*)d_in[0];
    const int*   wq    = (const int*)d_in[1];
    const float* scale = (const float*)d_in[2];
    const float* zp    = (const float*)d_in[3];
    const float* bias  = (const float*)d_in[4];
    float* out = (float*)d_out;

    convert_kernel<<<W_BLOCKS + X_BLOCKS, 256>>>(wq, scale, zp, x);

    static bool attr_set = false;
    if (!attr_set) {
        cudaFuncSetAttribute(gemm_kernel, cudaFuncAttributeMaxDynamicSharedMemorySize, SMEM_BYTES);
        attr_set = true;
    }
    dim3 grid(NDIM / TILE_N, MDIM / TILE_M);   // (32, 64)
    gemm_kernel<<<grid, 256, SMEM_BYTES>>>(bias, out);
}